// round 4
// baseline (speedup 1.0000x reference)
#include <cuda_runtime.h>

// ---------------------------------------------------------------------------
// MyViT patch embedding on GB300 (sm_103a)
//   images [64,3,224,224] f32 -> patchify -> A [12544,768]
//   C[m,n] = sum_k A[m,k] * W[n,k] + b[n]        (M=12544, N=768, K=768)
//   out [64,197,768]: row 0 per batch = class_token, rows 1..196 = tokens
// Strategy: fp32 exact math, packed fma.rn.f32x2 (2x FFMA throughput on sm_103a)
// ---------------------------------------------------------------------------

#define B_SZ      64
#define NPATCH    196          // 14*14
#define M_TOT     12544        // 64*196
#define K_TOT     768
#define N_TOT     768

// scratch for patchified A: 12544 x 768 floats = 38.5 MB (device global: allowed)
static __device__ float g_patches[M_TOT * K_TOT];

// ---------------- packed f32x2 helpers ----------------
__device__ __forceinline__ unsigned long long pk2(float lo, float hi) {
    unsigned long long r;
    asm("mov.b64 %0, {%1, %2};"
        : "=l"(r) : "r"(__float_as_uint(lo)), "r"(__float_as_uint(hi)));
    return r;
}
__device__ __forceinline__ unsigned long long dup2(float x) { return pk2(x, x); }
__device__ __forceinline__ void fma2(unsigned long long& d,
                                     unsigned long long a,
                                     unsigned long long b) {
    asm("fma.rn.f32x2 %0, %1, %2, %0;" : "+l"(d) : "l"(a), "l"(b));
}
__device__ __forceinline__ float2 up2(unsigned long long v) {
    unsigned lo, hi;
    asm("mov.b64 {%0, %1}, %2;" : "=r"(lo), "=r"(hi) : "l"(v));
    return make_float2(__uint_as_float(lo), __uint_as_float(hi));
}

// ---------------------------------------------------------------------------
// Kernel 1: patchify. One thread = one float4 of the patch matrix.
// dest d = c*256 + ph*16 + pw  (flatten order (c, ph, pw)), ps = 16.
// Exact grid: 12544*192 vec4 elements / 256 = 9408 blocks. No bounds check.
// ---------------------------------------------------------------------------
__global__ void patchify_kernel(const float* __restrict__ images) {
    int idx  = blockIdx.x * 256 + threadIdx.x;   // vec4 index into g_patches
    int m    = idx / 192;                        // token row (b*196 + p)
    int t    = idx - m * 192;                    // vec4 within 768-dim row
    int c    = t >> 6;                           // channel (t / 64)
    int rem  = t & 63;
    int ph   = rem >> 2;                         // row within patch
    int pw4  = (rem & 3) << 2;                   // col within patch (vec4 base)
    int b    = m / 196;
    int p    = m - b * 196;
    int pi   = p / 14;
    int pj   = p - pi * 14;
    int src  = (((b * 3 + c) * 224) + pi * 16 + ph) * 224 + pj * 16 + pw4;
    float4 v = *(const float4*)(images + src);
    *(float4*)(g_patches + (size_t)idx * 4) = v;
}

// ---------------------------------------------------------------------------
// Kernel 2: class-token broadcast into out[b, 0, :].
// 64*192 vec4 = 12288 threads = 48 blocks exactly.
// ---------------------------------------------------------------------------
__global__ void cls_kernel(const float* __restrict__ cls, float* __restrict__ out) {
    int idx = blockIdx.x * 256 + threadIdx.x;    // vec4 index
    int b   = idx / 192;
    int h4  = (idx - b * 192) * 4;
    *(float4*)(out + (size_t)b * 197 * 768 + h4) = *(const float4*)(cls + h4);
}

// ---------------------------------------------------------------------------
// Kernel 3: SGEMM (NT): C[m,n] = sum_k A[m,k]*W[n,k] + bias[n]
// 128x128 block tile, BK=16, 256 threads, 8x8 micro-tile, f32x2 accumulators.
// Epilogue scatters into out with the +1 token offset per batch.
// M=98*128, N=6*128, K=48*16 exactly -> no bounds checks anywhere.
// ---------------------------------------------------------------------------
__global__ void __launch_bounds__(256, 2)
vit_gemm_kernel(const float* __restrict__ Wmat,
                const float* __restrict__ bias,
                float* __restrict__ out) {
    __shared__ float As[16][132];   // [k][m], padded to break store conflicts
    __shared__ float Bs[16][132];   // [k][n]

    const int tid = threadIdx.x;
    const int tx  = tid & 15;       // 0..15 -> n micro
    const int ty  = tid >> 4;       // 0..15 -> m micro
    const int n0  = blockIdx.x * 128;
    const int m0  = blockIdx.y * 128;

    // global load mapping: vec id = tid (rows 0..63) and tid+256 (rows 64..127)
    const int lr = tid >> 2;            // 0..63
    const int lc = (tid & 3) << 2;      // 0,4,8,12

    const float* a0p = g_patches + (size_t)(m0 + lr) * K_TOT + lc;
    const float* a1p = a0p + (size_t)64 * K_TOT;
    const float* b0p = Wmat      + (size_t)(n0 + lr) * K_TOT + lc;
    const float* b1p = b0p + (size_t)64 * K_TOT;

    // prefetch k-tile 0
    float4 ra0 = *(const float4*)a0p;
    float4 ra1 = *(const float4*)a1p;
    float4 rb0 = *(const float4*)b0p;
    float4 rb1 = *(const float4*)b1p;

    unsigned long long acc[8][4];
    #pragma unroll
    for (int i = 0; i < 8; ++i)
        #pragma unroll
        for (int j = 0; j < 4; ++j)
            acc[i][j] = 0ull;

    for (int kt = 0; kt < 48; ++kt) {
        // commit prefetched tile to smem (transposed: [k][m] / [k][n])
        As[lc + 0][lr]      = ra0.x;  As[lc + 1][lr]      = ra0.y;
        As[lc + 2][lr]      = ra0.z;  As[lc + 3][lr]      = ra0.w;
        As[lc + 0][lr + 64] = ra1.x;  As[lc + 1][lr + 64] = ra1.y;
        As[lc + 2][lr + 64] = ra1.z;  As[lc + 3][lr + 64] = ra1.w;
        Bs[lc + 0][lr]      = rb0.x;  Bs[lc + 1][lr]      = rb0.y;
        Bs[lc + 2][lr]      = rb0.z;  Bs[lc + 3][lr]      = rb0.w;
        Bs[lc + 0][lr + 64] = rb1.x;  Bs[lc + 1][lr + 64] = rb1.y;
        Bs[lc + 2][lr + 64] = rb1.z;  Bs[lc + 3][lr + 64] = rb1.w;
        __syncthreads();

        // prefetch next tile into registers (hidden behind compute)
        if (kt < 47) {
            int off = (kt + 1) * 16;
            ra0 = *(const float4*)(a0p + off);
            ra1 = *(const float4*)(a1p + off);
            rb0 = *(const float4*)(b0p + off);
            rb1 = *(const float4*)(b1p + off);
        }

        #pragma unroll
        for (int k = 0; k < 16; ++k) {
            float4 av0 = *(const float4*)&As[k][ty * 4];
            float4 av1 = *(const float4*)&As[k][64 + ty * 4];
            float4 bv0 = *(const float4*)&Bs[k][tx * 4];
            float4 bv1 = *(const float4*)&Bs[k][64 + tx * 4];

            unsigned long long bp[4];
            bp[0] = pk2(bv0.x, bv0.y);
            bp[1] = pk2(bv0.z, bv0.w);
            bp[2] = pk2(bv1.x, bv1.y);
            bp[3] = pk2(bv1.z, bv1.w);

            float av[8] = {av0.x, av0.y, av0.z, av0.w,
                           av1.x, av1.y, av1.z, av1.w};
            #pragma unroll
            for (int i = 0; i < 8; ++i) {
                unsigned long long ad = dup2(av[i]);
                #pragma unroll
                for (int j = 0; j < 4; ++j)
                    fma2(acc[i][j], ad, bp[j]);
            }
        }
        __syncthreads();
    }

    // epilogue: add bias, scatter to out[b, 1+p, n]
    #pragma unroll
    for (int i = 0; i < 8; ++i) {
        int mrow = m0 + ((i < 4) ? (ty * 4 + i) : (64 + ty * 4 + (i - 4)));
        int bb   = mrow / 196;
        int pp   = mrow - bb * 196;
        float* orow = out + ((size_t)bb * 197 + pp + 1) * 768;
        #pragma unroll
        for (int j = 0; j < 4; ++j) {
            int n = n0 + ((j < 2) ? (tx * 4 + 2 * j) : (64 + tx * 4 + 2 * (j - 2)));
            float2 v = up2(acc[i][j]);
            v.x += __ldg(bias + n);
            v.y += __ldg(bias + n + 1);
            *(float2*)(orow + n) = v;
        }
    }
}

// ---------------------------------------------------------------------------
// launch: patchify -> (cls broadcast) -> GEMM.  Graph-capturable: kernel
// launches only, no sync, no alloc.
// Inputs (metadata order): images, W, b, class_token; out f32 [64,197,768].
// ---------------------------------------------------------------------------
extern "C" void kernel_launch(void* const* d_in, const int* in_sizes, int n_in,
                              void* d_out, int out_size) {
    const float* images = (const float*)d_in[0];
    const float* Wm     = (const float*)d_in[1];
    const float* bias   = (const float*)d_in[2];
    const float* cls    = (const float*)d_in[3];
    float* out = (float*)d_out;

    patchify_kernel<<<9408, 256>>>(images);          // 12544*192/256 exact
    cls_kernel<<<48, 256>>>(cls, out);               // 64*192/256 exact
    dim3 grid(N_TOT / 128, M_TOT / 128);             // (6, 98)
    vit_gemm_kernel<<<grid, 256>>>(Wm, bias, out);
}

// round 12
// speedup vs baseline: 1.7132x; 1.7132x over previous
#include <cuda_runtime.h>
#include <cuda_bf16.h>
#include <cstdint>

// ---------------------------------------------------------------------------
// MyViT patch embedding on GB300 (sm_103a, but harness PTX target = sm_103
// baseline -> no tcgen05). Tensor path: mma.sync bf16 (HMMA) with 3xBF16
// error compensation:
//   C = Ah*Wh + Al*Wh + Ah*Wl  (+ bias), dropped lo*lo term ~2^-18 rel.
// Folded as one GEMM with K' = 3*768 = 2304 over segment-selected pointers.
// ---------------------------------------------------------------------------

#define M_TOT 12544
#define K_TOT 768
#define N_TOT 768

#define TM 256
#define TN 128
#define BK 32
#define KCHUNKS 72          // 3 segments * 24 chunks (768/32)
#define STAGES 4
#define STAGE_BYTES 24576   // A 16KB + B 8KB
#define GEMM_SMEM (STAGES * STAGE_BYTES)   // 96 KB dynamic

// device scratch
static __device__ __nv_bfloat16 g_Ah[(size_t)M_TOT * K_TOT];
static __device__ __nv_bfloat16 g_Al[(size_t)M_TOT * K_TOT];
static __device__ __nv_bfloat16 g_Wh[(size_t)N_TOT * K_TOT];
static __device__ __nv_bfloat16 g_Wl[(size_t)N_TOT * K_TOT];

__device__ __forceinline__ uint32_t smem_to_u32(const void* p) {
    uint32_t a;
    asm("{ .reg .u64 t; cvta.to.shared.u64 t, %1; cvt.u32.u64 %0, t; }"
        : "=r"(a) : "l"(p));
    return a;
}

#define CP_ASYNC16(saddr, gptr) \
    asm volatile("cp.async.cg.shared.global [%0], [%1], 16;" \
                 :: "r"(saddr), "l"(gptr) : "memory")
#define CP_COMMIT() asm volatile("cp.async.commit_group;" ::: "memory")
#define CP_WAIT2()  asm volatile("cp.async.wait_group 2;" ::: "memory")

#define LDSM_X4(r0, r1, r2, r3, addr) \
    asm volatile("ldmatrix.sync.aligned.m8n8.x4.shared.b16 {%0,%1,%2,%3}, [%4];" \
                 : "=r"(r0), "=r"(r1), "=r"(r2), "=r"(r3) : "r"(addr))

#define MMA_BF16(d, a, b) \
    asm volatile("mma.sync.aligned.m16n8k16.row.col.f32.bf16.bf16.f32 " \
                 "{%0,%1,%2,%3}, {%4,%5,%6,%7}, {%8,%9}, {%0,%1,%2,%3};" \
                 : "+f"((d)[0]), "+f"((d)[1]), "+f"((d)[2]), "+f"((d)[3]) \
                 : "r"((a)[0]), "r"((a)[1]), "r"((a)[2]), "r"((a)[3]), \
                   "r"((b)[0]), "r"((b)[1]))

// swizzle: 64B rows, chunk(16B)' = chunk ^ ((row>>1)&3)  -> conflict-free
// STS (cp.async) and ldmatrix (8 rows x 16B cover 128B exactly).
__device__ __forceinline__ uint32_t swz(uint32_t row, uint32_t chunk) {
    return row * 64u + ((chunk ^ ((row >> 1) & 3u)) << 4);
}

// split fp32 -> (hi, lo) bf16
__device__ __forceinline__ void split_bf16(float v, __nv_bfloat16& h, __nv_bfloat16& l) {
    h = __float2bfloat16(v);
    l = __float2bfloat16(v - __bfloat162float(h));
}

// ---------------------------------------------------------------------------
// Kernel 1: patchify + hi/lo split. 12544*96 vec8 / 256 = 4704 blocks exact.
// ---------------------------------------------------------------------------
__global__ void patchify_split_kernel(const float* __restrict__ images) {
    int idx = blockIdx.x * 256 + threadIdx.x;   // vec8 index
    int m   = idx / 96;
    int t   = idx - m * 96;
    int c   = t >> 5;
    int rem = t & 31;
    int ph  = rem >> 1;
    int pw8 = (rem & 1) << 3;
    int b   = m / 196;
    int p   = m - b * 196;
    int pi  = p / 14;
    int pj  = p - pi * 14;
    int src = (((b * 3 + c) * 224) + pi * 16 + ph) * 224 + pj * 16 + pw8;
    float4 v0 = *(const float4*)(images + src);
    float4 v1 = *(const float4*)(images + src + 4);
    float f[8] = {v0.x, v0.y, v0.z, v0.w, v1.x, v1.y, v1.z, v1.w};
    __nv_bfloat16 h[8], l[8];
#pragma unroll
    for (int i = 0; i < 8; ++i) split_bf16(f[i], h[i], l[i]);
    *((uint4*)g_Ah + idx) = *(const uint4*)h;
    *((uint4*)g_Al + idx) = *(const uint4*)l;
}

// ---------------------------------------------------------------------------
// Kernel 2: W hi/lo split. 73728 vec8 / 256 = 288 blocks exact.
// ---------------------------------------------------------------------------
__global__ void wsplit_kernel(const float* __restrict__ Wm) {
    int idx = blockIdx.x * 256 + threadIdx.x;
    float4 v0 = *(const float4*)(Wm + (size_t)idx * 8);
    float4 v1 = *(const float4*)(Wm + (size_t)idx * 8 + 4);
    float f[8] = {v0.x, v0.y, v0.z, v0.w, v1.x, v1.y, v1.z, v1.w};
    __nv_bfloat16 h[8], l[8];
#pragma unroll
    for (int i = 0; i < 8; ++i) split_bf16(f[i], h[i], l[i]);
    *((uint4*)g_Wh + idx) = *(const uint4*)h;
    *((uint4*)g_Wl + idx) = *(const uint4*)l;
}

// ---------------------------------------------------------------------------
// Kernel 3: class token -> out[b,0,:]. 48 blocks exact.
// ---------------------------------------------------------------------------
__global__ void cls_kernel(const float* __restrict__ cls, float* __restrict__ out) {
    int idx = blockIdx.x * 256 + threadIdx.x;
    int b   = idx / 192;
    int h4  = (idx - b * 192) * 4;
    *(float4*)(out + (size_t)b * 197 * 768 + h4) = *(const float4*)(cls + h4);
}

// ---------------------------------------------------------------------------
// Kernel 4: HMMA GEMM. 256x128 tile, BK=32, 8 warps (4x2), warp tile 64x64,
// 4-stage cp.async pipeline. grid = (768/128, 12544/256) = (6, 49).
// ---------------------------------------------------------------------------
__global__ void __launch_bounds__(256, 1)
vit_gemm_hmma(const float* __restrict__ bias, float* __restrict__ out) {
    extern __shared__ char smem[];
    const uint32_t sb = smem_to_u32(smem);

    const int tid  = threadIdx.x;
    const int lane = tid & 31;
    const int wid  = tid >> 5;
    const int wm   = wid >> 1;           // 0..3 -> m offset wm*64
    const int wn   = wid & 1;            // 0..1 -> n offset wn*64
    const int n0   = blockIdx.x * TN;
    const int m0   = blockIdx.y * TM;

    // ---- per-thread cp.async source/dest invariants ----
    // A: 1024 16B-chunks (256 rows x 4), ids tid + i*256, i<4
    // B: 512 chunks (128 rows x 4), ids tid + i*256, i<2
    uint32_t aSm[4], bSm[2];
    size_t   aRow[4], bRow[2];
#pragma unroll
    for (int i = 0; i < 4; ++i) {
        int id = tid + i * 256;
        uint32_t R = id >> 2, c = id & 3;
        aSm[i]  = swz(R, c);                                   // + stage base
        aRow[i] = (size_t)(m0 + R) * K_TOT + c * 8;            // + koff, + seg base
    }
#pragma unroll
    for (int i = 0; i < 2; ++i) {
        int id = tid + i * 256;
        uint32_t R = id >> 2, c = id & 3;
        bSm[i]  = 16384u + swz(R, c);
        bRow[i] = (size_t)(n0 + R) * K_TOT + c * 8;
    }

    // ---- ldmatrix swizzled offsets (relative to stage base) ----
    uint32_t offA[4][2], offB[4][2];
#pragma unroll
    for (int mi = 0; mi < 4; ++mi)
#pragma unroll
        for (int kk = 0; kk < 2; ++kk) {
            uint32_t r = wm * 64 + mi * 16 + (lane & 15);
            uint32_t c = kk * 2 + (lane >> 4);
            offA[mi][kk] = swz(r, c);
        }
#pragma unroll
    for (int nj = 0; nj < 4; ++nj)
#pragma unroll
        for (int kk = 0; kk < 2; ++kk) {
            uint32_t mtx = lane >> 3;                    // 0..3
            uint32_t r = wn * 64 + nj * 16 + ((mtx >> 1) << 3) + (lane & 7);
            uint32_t c = kk * 2 + (mtx & 1);
            offB[nj][kk] = 16384u + swz(r, c);
        }

    float acc[4][8][4];
#pragma unroll
    for (int mi = 0; mi < 4; ++mi)
#pragma unroll
        for (int n8 = 0; n8 < 8; ++n8)
#pragma unroll
            for (int q = 0; q < 4; ++q) acc[mi][n8][q] = 0.f;

    // fetch one stage of chunk kt
    auto fetch = [&](int kt, int stage) {
        int seg  = kt / 24;
        int koff = (kt - seg * 24) * BK;
        const __nv_bfloat16* Asrc = (seg == 1) ? g_Al : g_Ah;
        const __nv_bfloat16* Bsrc = (seg == 2) ? g_Wl : g_Wh;
        uint32_t stb = sb + stage * STAGE_BYTES;
#pragma unroll
        for (int i = 0; i < 4; ++i)
            CP_ASYNC16(stb + aSm[i], (const char*)(Asrc + aRow[i] + koff));
#pragma unroll
        for (int i = 0; i < 2; ++i)
            CP_ASYNC16(stb + bSm[i], (const char*)(Bsrc + bRow[i] + koff));
    };

    // prologue: stages 0..2
#pragma unroll
    for (int p = 0; p < 3; ++p) { fetch(p, p); CP_COMMIT(); }

#pragma unroll 1
    for (int kt = 0; kt < KCHUNKS; ++kt) {
        CP_WAIT2();            // stage kt landed
        __syncthreads();       // all warps done with stage (kt-1)%4
        if (kt + 3 < KCHUNKS) fetch(kt + 3, (kt + 3) & 3);
        CP_COMMIT();

        const uint32_t stb = sb + (kt & 3) * STAGE_BYTES;
#pragma unroll
        for (int kk = 0; kk < 2; ++kk) {
            uint32_t a[4][4], b[8][2];
#pragma unroll
            for (int mi = 0; mi < 4; ++mi)
                LDSM_X4(a[mi][0], a[mi][1], a[mi][2], a[mi][3], stb + offA[mi][kk]);
#pragma unroll
            for (int nj = 0; nj < 4; ++nj)
                LDSM_X4(b[2 * nj][0], b[2 * nj][1], b[2 * nj + 1][0], b[2 * nj + 1][1],
                        stb + offB[nj][kk]);
#pragma unroll
            for (int mi = 0; mi < 4; ++mi)
#pragma unroll
                for (int n8 = 0; n8 < 8; ++n8)
                    MMA_BF16(acc[mi][n8], a[mi], b[n8]);
        }
    }

    // ---- epilogue: bias + scatter into out[b, 1+p, n] ----
    // bias per n8 tile (col depends only on n8)
    float2 bv[8];
    {
        int cbase = n0 + wn * 64 + ((lane & 3) << 1);
#pragma unroll
        for (int n8 = 0; n8 < 8; ++n8) {
            int cc = cbase + n8 * 8;
            bv[n8] = make_float2(__ldg(bias + cc), __ldg(bias + cc + 1));
        }
    }
#pragma unroll
    for (int mi = 0; mi < 4; ++mi) {
        int m_lo = m0 + wm * 64 + mi * 16 + (lane >> 2);
        int m_hi = m_lo + 8;
        int b_lo = m_lo / 196, p_lo = m_lo - b_lo * 196;
        int b_hi = m_hi / 196, p_hi = m_hi - b_hi * 196;
        float* r_lo = out + ((size_t)b_lo * 197 + p_lo + 1) * 768;
        float* r_hi = out + ((size_t)b_hi * 197 + p_hi + 1) * 768;
        int cbase = n0 + wn * 64 + ((lane & 3) << 1);
#pragma unroll
        for (int n8 = 0; n8 < 8; ++n8) {
            int cc = cbase + n8 * 8;
            *(float2*)(r_lo + cc) =
                make_float2(acc[mi][n8][0] + bv[n8].x, acc[mi][n8][1] + bv[n8].y);
            *(float2*)(r_hi + cc) =
                make_float2(acc[mi][n8][2] + bv[n8].x, acc[mi][n8][3] + bv[n8].y);
        }
    }
}

// ---------------------------------------------------------------------------
// launch
// ---------------------------------------------------------------------------
extern "C" void kernel_launch(void* const* d_in, const int* in_sizes, int n_in,
                              void* d_out, int out_size) {
    const float* images = (const float*)d_in[0];
    const float* Wm     = (const float*)d_in[1];
    const float* bias   = (const float*)d_in[2];
    const float* cls    = (const float*)d_in[3];
    float* out = (float*)d_out;

    cudaFuncSetAttribute(vit_gemm_hmma,
                         cudaFuncAttributeMaxDynamicSharedMemorySize, GEMM_SMEM);

    patchify_split_kernel<<<4704, 256>>>(images);
    wsplit_kernel<<<288, 256>>>(Wm);
    cls_kernel<<<48, 256>>>(cls, out);
    dim3 grid(N_TOT / TN, M_TOT / TM);   // (6, 49)
    vit_gemm_hmma<<<grid, 256, GEMM_SMEM>>>(bias, out);
}